// round 10
// baseline (speedup 1.0000x reference)
#include <cuda_runtime.h>
#include <math.h>

#define B_  4
#define N_  8192
#define M_  8192
#define FEAT 64
#define KNN_K 16
#define K4  4
#define S_  8
#define SPLIT_M (M_ / S_)          // 1024 == one smem tile
#define P1_THREADS 128
#define QPT 2                       // queries per thread
#define BUF 11
#define S2_THREADS 256
#define S2_WARPS 8
#define FULLMASK 0xffffffffu

// Static device scratch (no allocation allowed).
__device__ int   g_knn_idx[B_ * N_ * KNN_K];
__device__ float g_cand_d[S_][KNN_K][B_ * N_];
__device__ int   g_cand_i[S_][KNN_K][B_ * N_];

__device__ __forceinline__ void insert16(float (&dl)[KNN_K], int (&il)[KNN_K],
                                         float d, int i)
{
    if (d < dl[KNN_K - 1]) {
        dl[KNN_K - 1] = d;
        il[KNN_K - 1] = i;
#pragma unroll
        for (int t = KNN_K - 1; t > 0; --t) {
            bool sw = dl[t] < dl[t - 1];
            float flo = sw ? dl[t]     : dl[t - 1];
            float fhi = sw ? dl[t - 1] : dl[t];
            int   ilo = sw ? il[t]     : il[t - 1];
            int   ihi = sw ? il[t - 1] : il[t];
            dl[t - 1] = flo; dl[t] = fhi;
            il[t - 1] = ilo; il[t] = ihi;
        }
    }
}

// ---------------------------------------------------------------------------
// Phase 1: per-split distance scan + buffered exact top-16, 2 queries/thread.
// Distance bits match XLA reference exactly:
//   q2/o2: plain-rounded ((x*x + y*y) + z*z), no fma
//   cross: forward fma chain fma(z,oz, fma(y,oy, rn(x*ox)))
//   d2   : fmaf(-2, c, fadd(q2,o2))  ==  fsub(fadd(q2,o2), fmul(2,c))
// One LDS.128 + loop overhead amortized over 2 query evals. Appends go to a
// per-query smem FIFO via running byte-offsets; flushes batch the insertion
// sort so all lanes insert in parallel. Single tile per block (no tile loop).
// ---------------------------------------------------------------------------
__global__ void __launch_bounds__(P1_THREADS, 5) knn_part_kernel(
    const float* __restrict__ orig, const float* __restrict__ query)
{
    __shared__ float4 tile[SPLIT_M];                    // 16 KB
    __shared__ float  bufD[BUF][P1_THREADS * QPT];      // 11 KB
    __shared__ int    bufI[BUF][P1_THREADS * QPT];      // 11 KB

    const int b = blockIdx.y;
    const int s = blockIdx.z;
    const int tid = threadIdx.x;
    const int qA = blockIdx.x * (P1_THREADS * QPT) + tid;
    const int qB = qA + P1_THREADS;
    const int mbase = s * SPLIT_M;

    const float* __restrict__ ox = orig + (size_t)b * 3 * M_;
    const float* __restrict__ oy = ox + M_;
    const float* __restrict__ oz = ox + 2 * M_;

    for (int i = tid; i < SPLIT_M; i += P1_THREADS) {
        float x = ox[mbase + i];
        float y = oy[mbase + i];
        float z = oz[mbase + i];
        float o2 = __fadd_rn(__fadd_rn(__fmul_rn(x, x), __fmul_rn(y, y)),
                             __fmul_rn(z, z));
        tile[i] = make_float4(x, y, z, o2);
    }

    const float qxA = query[(b * 3 + 0) * N_ + qA];
    const float qyA = query[(b * 3 + 1) * N_ + qA];
    const float qzA = query[(b * 3 + 2) * N_ + qA];
    const float q2A = __fadd_rn(__fadd_rn(__fmul_rn(qxA, qxA), __fmul_rn(qyA, qyA)),
                                __fmul_rn(qzA, qzA));
    const float qxB = query[(b * 3 + 0) * N_ + qB];
    const float qyB = query[(b * 3 + 1) * N_ + qB];
    const float qzB = query[(b * 3 + 2) * N_ + qB];
    const float q2B = __fadd_rn(__fadd_rn(__fmul_rn(qxB, qxB), __fmul_rn(qyB, qyB)),
                                __fmul_rn(qzB, qzB));

    float dlA[KNN_K], dlB[KNN_K];
    int   ilA[KNN_K], ilB[KNN_K];
    const float INF = __int_as_float(0x7f800000);
#pragma unroll
    for (int j = 0; j < KNN_K; ++j) {
        dlA[j] = INF; ilA[j] = 0;
        dlB[j] = INF; ilB[j] = 0;
    }

    const int ROWB = P1_THREADS * QPT * 4;              // row stride in bytes
    char* const bDA = (char*)&bufD[0][0] + tid * 4;
    char* const bIA = (char*)&bufI[0][0] + tid * 4;
    char* const bDB = bDA + P1_THREADS * 4;
    char* const bIB = bIA + P1_THREADS * 4;
    int offA = 0, offB = 0;
    const int offFlushLim = 3 * ROWB;                   // keep 8 rows headroom

    __syncthreads();

    for (int m0 = 0; m0 < SPLIT_M; m0 += 8) {
#pragma unroll
        for (int u = 0; u < 8; ++u) {
            float4 p = tile[m0 + u];
            float crA = __fmul_rn(qxA, p.x);
            crA = fmaf(qyA, p.y, crA);
            crA = fmaf(qzA, p.z, crA);
            float dA = fmaf(-2.0f, crA, __fadd_rn(q2A, p.w));
            float crB = __fmul_rn(qxB, p.x);
            crB = fmaf(qyB, p.y, crB);
            crB = fmaf(qzB, p.z, crB);
            float dB = fmaf(-2.0f, crB, __fadd_rn(q2B, p.w));
            if (dA < dlA[KNN_K - 1]) {
                *(float*)(bDA + offA) = dA;
                *(int*)(bIA + offA) = mbase + m0 + u;
                offA += ROWB;
            }
            if (dB < dlB[KNN_K - 1]) {
                *(float*)(bDB + offB) = dB;
                *(int*)(bIB + offB) = mbase + m0 + u;
                offB += ROWB;
            }
        }
        if (__any_sync(FULLMASK, (offA > offFlushLim) | (offB > offFlushLim))) {
            const int cA = offA / ROWB;
            for (int j = 0; j < cA; ++j)
                insert16(dlA, ilA, bufD[j][tid], bufI[j][tid]);
            const int cB = offB / ROWB;
            for (int j = 0; j < cB; ++j)
                insert16(dlB, ilB, bufD[j][tid + P1_THREADS], bufI[j][tid + P1_THREADS]);
            offA = 0;
            offB = 0;
        }
    }
    // tail flush
    {
        const int cA = offA / ROWB;
        for (int j = 0; j < cA; ++j)
            insert16(dlA, ilA, bufD[j][tid], bufI[j][tid]);
        const int cB = offB / ROWB;
        for (int j = 0; j < cB; ++j)
            insert16(dlB, ilB, bufD[j][tid + P1_THREADS], bufI[j][tid + P1_THREADS]);
    }

    const int gqA = b * N_ + qA;
    const int gqB = b * N_ + qB;
#pragma unroll
    for (int j = 0; j < KNN_K; ++j) {
        g_cand_d[s][j][gqA] = dlA[j];
        g_cand_i[s][j][gqA] = ilA[j];
        g_cand_d[s][j][gqB] = dlB[j];
        g_cand_i[s][j][gqB] = ilB[j];
    }
}

// ---------------------------------------------------------------------------
// Phase 2: stable 8-way tournament merge of per-split sorted top-16 lists.
// Lexicographic (d, idx) == jax.lax.top_k tie-breaking (lowest index first).
// ---------------------------------------------------------------------------
__global__ void __launch_bounds__(128) knn_merge_kernel()
{
    const int q = blockIdx.x * 128 + threadIdx.x;   // global query id
    const float INF = __int_as_float(0x7f800000);

    float hd[S_];
    int   hi[S_];
    int   pp[S_];
#pragma unroll
    for (int s = 0; s < S_; ++s) {
        hd[s] = g_cand_d[s][0][q];
        hi[s] = g_cand_i[s][0][q];
        pp[s] = 0;
    }

    int* outp = g_knn_idx + (size_t)q * KNN_K;

#pragma unroll
    for (int step = 0; step < KNN_K; ++step) {
        int ws = 0;
        float wd = hd[0];
        int wi = hi[0];
#pragma unroll
        for (int s = 1; s < S_; ++s) {
            bool better = (hd[s] < wd) || (hd[s] == wd && hi[s] < wi);
            if (better) { ws = s; wd = hd[s]; wi = hi[s]; }
        }
        outp[step] = wi;
#pragma unroll
        for (int s = 0; s < S_; ++s) {
            if (ws == s) {
                ++pp[s];
                if (pp[s] < KNN_K) {
                    hd[s] = g_cand_d[s][pp[s]][q];
                    hi[s] = g_cand_i[s][pp[s]][q];
                } else {
                    hd[s] = INF;
                    hi[s] = 0x7fffffff;
                }
            }
        }
    }
}

// ---------------------------------------------------------------------------
// Phase 3: fused MLP0 (3->64) + max-pool + MLP1 (64->64, k<4) + sigmoid gate
// + gather + weighted sum. Warp-per-query, BN folded. 8 warps/block.
// ---------------------------------------------------------------------------
__global__ void __launch_bounds__(S2_THREADS) fuse_kernel(
    const float* __restrict__ orig, const float* __restrict__ query,
    const float* __restrict__ local_feat,
    const float* __restrict__ w0, const float* __restrict__ b0,
    const float* __restrict__ g0, const float* __restrict__ be0,
    const float* __restrict__ m0, const float* __restrict__ v0,
    const float* __restrict__ w1, const float* __restrict__ b1,
    const float* __restrict__ g1, const float* __restrict__ be1,
    const float* __restrict__ m1, const float* __restrict__ v1,
    const float* __restrict__ w2, const float* __restrict__ b2,
    float* __restrict__ out)
{
    __shared__ float sW0[3][FEAT];
    __shared__ float sB0[FEAT];
    __shared__ float sW1[FEAT][FEAT + 1];   // +1 pad: conflict-free row reads
    __shared__ float sB1[FEAT];
    __shared__ float sW2[2 * FEAT];
    __shared__ float sS1[FEAT];
    __shared__ float sF0[S2_WARPS][FEAT][K4];  // [cp][k] -> float4 broadcast read

    const int tid = threadIdx.x;

    if (tid < FEAT) {
        float s0 = g0[tid] / sqrtf(v0[tid] + 1e-5f);
        sB0[tid] = (b0[tid] - m0[tid]) * s0 + be0[tid];
        sW0[0][tid] = w0[tid * 3 + 0] * s0;
        sW0[1][tid] = w0[tid * 3 + 1] * s0;
        sW0[2][tid] = w0[tid * 3 + 2] * s0;
        float s1 = g1[tid] / sqrtf(v1[tid] + 1e-5f);
        sS1[tid] = s1;
        sB1[tid] = (b1[tid] - m1[tid]) * s1 + be1[tid];
        sW2[tid] = w2[tid];
        sW2[tid + FEAT] = w2[tid + FEAT];
    }
    __syncthreads();
    for (int i = tid; i < FEAT * FEAT; i += S2_THREADS) {
        int ch = i >> 6;
        sW1[ch][i & 63] = w1[i] * sS1[ch];
    }
    __syncthreads();

    const int warp = tid >> 5;
    const int lane = tid & 31;
    const int qid = blockIdx.x * S2_WARPS + warp;
    const int b = qid >> 13;          // / N_
    const int n = qid & (N_ - 1);

    const int* kp = g_knn_idx + (size_t)qid * KNN_K;
    int kidx = (lane < KNN_K) ? kp[lane] : 0;

    const float qx = query[(b * 3 + 0) * N_ + n];
    const float qy = query[(b * 3 + 1) * N_ + n];
    const float qz = query[(b * 3 + 2) * N_ + n];

    float px = 0.f, py = 0.f, pz = 0.f;
    {
        const float* ob = orig + (size_t)b * 3 * M_;
        if (lane < KNN_K) {
            px = ob[kidx];
            py = ob[M_ + kidx];
            pz = ob[2 * M_ + kidx];
        }
    }

    const int c0 = lane, c1 = lane + 32;
    const float w0x0 = sW0[0][c0], w0y0 = sW0[1][c0], w0z0 = sW0[2][c0], bb00 = sB0[c0];
    const float w0x1 = sW0[0][c1], w0y1 = sW0[1][c1], w0z1 = sW0[2][c1], bb01 = sB0[c1];

    float fg0 = 0.f, fg1 = 0.f;   // relu >= 0 so 0 init == max

#pragma unroll
    for (int k = 0; k < KNN_K; ++k) {
        float rx = __shfl_sync(FULLMASK, px, k) - qx;
        float ry = __shfl_sync(FULLMASK, py, k) - qy;
        float rz = __shfl_sync(FULLMASK, pz, k) - qz;
        float a0 = fmaf(w0x0, rx, fmaf(w0y0, ry, fmaf(w0z0, rz, bb00)));
        float a1 = fmaf(w0x1, rx, fmaf(w0y1, ry, fmaf(w0z1, rz, bb01)));
        a0 = fmaxf(a0, 0.f);
        a1 = fmaxf(a1, 0.f);
        fg0 = fmaxf(fg0, a0);
        fg1 = fmaxf(fg1, a1);
        if (k < K4) {
            sF0[warp][c0][k] = a0;
            sF0[warp][c1][k] = a1;
        }
    }
    __syncwarp();

    const float bb10 = sB1[c0], bb11 = sB1[c1];
    float ra0 = bb10, ra1 = bb10, ra2 = bb10, ra3 = bb10;
    float rb0 = bb11, rb1 = bb11, rb2 = bb11, rb3 = bb11;
#pragma unroll
    for (int cp = 0; cp < FEAT; ++cp) {
        float wa = sW1[c0][cp];
        float wb = sW1[c1][cp];
        float4 f = *reinterpret_cast<const float4*>(&sF0[warp][cp][0]); // broadcast
        ra0 = fmaf(wa, f.x, ra0); ra1 = fmaf(wa, f.y, ra1);
        ra2 = fmaf(wa, f.z, ra2); ra3 = fmaf(wa, f.w, ra3);
        rb0 = fmaf(wb, f.x, rb0); rb1 = fmaf(wb, f.y, rb1);
        rb2 = fmaf(wb, f.z, rb2); rb3 = fmaf(wb, f.w, rb3);
    }
    float rf0[K4], rf1[K4];
    rf0[0] = fmaxf(ra0, 0.f); rf0[1] = fmaxf(ra1, 0.f);
    rf0[2] = fmaxf(ra2, 0.f); rf0[3] = fmaxf(ra3, 0.f);
    rf1[0] = fmaxf(rb0, 0.f); rf1[1] = fmaxf(rb1, 0.f);
    rf1[2] = fmaxf(rb2, 0.f); rf1[3] = fmaxf(rb3, 0.f);

    const float w2a = sW2[c0], w2b = sW2[c1];
    const float w2ga = sW2[FEAT + c0], w2gb = sW2[FEAT + c1];
    const float bias2 = b2[0];
    const float* lf = local_feat + (size_t)b * FEAT * M_;

    float o0 = 0.f, o1 = 0.f;
#pragma unroll
    for (int k = 0; k < K4; ++k) {
        float part = w2a * rf0[k] + w2b * rf1[k] + w2ga * fg0 + w2gb * fg1;
#pragma unroll
        for (int sdown = 16; sdown > 0; sdown >>= 1)
            part += __shfl_xor_sync(FULLMASK, part, sdown);
        float wk = 1.0f / (1.0f + expf(-(part + bias2)));
        int mk = __shfl_sync(FULLMASK, kidx, k);
        float pf0 = lf[(size_t)c0 * M_ + mk];
        float pf1 = lf[(size_t)c1 * M_ + mk];
        o0 += (1.0f - wk) * rf0[k] + wk * pf0;
        o1 += (1.0f - wk) * rf1[k] + wk * pf1;
    }

    out[((size_t)b * FEAT + c0) * N_ + n] = o0;
    out[((size_t)b * FEAT + c1) * N_ + n] = o1;
}

// ---------------------------------------------------------------------------
extern "C" void kernel_launch(void* const* d_in, const int* in_sizes, int n_in,
                              void* d_out, int out_size)
{
    (void)in_sizes; (void)n_in; (void)out_size;
    const float* orig  = (const float*)d_in[0];
    const float* query = (const float*)d_in[1];
    const float* lf    = (const float*)d_in[2];
    const float* w0 = (const float*)d_in[3];
    const float* b0 = (const float*)d_in[4];
    const float* g0 = (const float*)d_in[5];
    const float* be0 = (const float*)d_in[6];
    const float* m0 = (const float*)d_in[7];
    const float* v0 = (const float*)d_in[8];
    const float* w1 = (const float*)d_in[9];
    const float* b1 = (const float*)d_in[10];
    const float* g1 = (const float*)d_in[11];
    const float* be1 = (const float*)d_in[12];
    const float* m1 = (const float*)d_in[13];
    const float* v1 = (const float*)d_in[14];
    const float* w2 = (const float*)d_in[15];
    const float* b2 = (const float*)d_in[16];
    float* out = (float*)d_out;

    dim3 g1d(N_ / (P1_THREADS * QPT), B_, S_);
    knn_part_kernel<<<g1d, P1_THREADS>>>(orig, query);

    knn_merge_kernel<<<(B_ * N_) / 128, 128>>>();

    fuse_kernel<<<(B_ * N_) / S2_WARPS, S2_THREADS>>>(
        orig, query, lf,
        w0, b0, g0, be0, m0, v0,
        w1, b1, g1, be1, m1, v1,
        w2, b2, out);
}

// round 13
// speedup vs baseline: 1.2888x; 1.2888x over previous
#include <cuda_runtime.h>
#include <math.h>

#define B_  4
#define N_  8192
#define M_  8192
#define FEAT 64
#define KNN_K 16
#define K4  4
#define S_  4
#define SPLIT_M (M_ / S_)          // 2048
#define TILE1 1024                  // points per smem tile
#define TILE_PAIRS (TILE1 / 2)      // 512 point-pairs
#define P1_THREADS 128
#define BUF 15
#define S2_THREADS 256
#define S2_WARPS 8
#define FULLMASK 0xffffffffu

// Static device scratch (no allocation allowed).
__device__ int   g_knn_idx[B_ * N_ * KNN_K];
__device__ float g_cand_d[S_][KNN_K][B_ * N_];
__device__ int   g_cand_i[S_][KNN_K][B_ * N_];

typedef unsigned long long ull;

__device__ __forceinline__ ull pack2(float lo, float hi) {
    ull r;
    asm("mov.b64 %0, {%1, %2};" : "=l"(r) : "f"(lo), "f"(hi));
    return r;
}
__device__ __forceinline__ void unpack2(ull v, float& lo, float& hi) {
    asm("mov.b64 {%0, %1}, %2;" : "=f"(lo), "=f"(hi) : "l"(v));
}
__device__ __forceinline__ ull mul2(ull a, ull b) {
    ull r;
    asm("mul.rn.f32x2 %0, %1, %2;" : "=l"(r) : "l"(a), "l"(b));
    return r;
}
__device__ __forceinline__ ull add2(ull a, ull b) {
    ull r;
    asm("add.rn.f32x2 %0, %1, %2;" : "=l"(r) : "l"(a), "l"(b));
    return r;
}
__device__ __forceinline__ ull fma2(ull a, ull b, ull c) {
    ull r;
    asm("fma.rn.f32x2 %0, %1, %2, %3;" : "=l"(r) : "l"(a), "l"(b), "l"(c));
    return r;
}

__device__ __forceinline__ void insert16(float (&dl)[KNN_K], int (&il)[KNN_K],
                                         float d, int i)
{
    if (d < dl[KNN_K - 1]) {
        dl[KNN_K - 1] = d;
        il[KNN_K - 1] = i;
#pragma unroll
        for (int t = KNN_K - 1; t > 0; --t) {
            bool sw = dl[t] < dl[t - 1];
            float flo = sw ? dl[t]     : dl[t - 1];
            float fhi = sw ? dl[t - 1] : dl[t];
            int   ilo = sw ? il[t]     : il[t - 1];
            int   ihi = sw ? il[t - 1] : il[t];
            dl[t - 1] = flo; dl[t] = fhi;
            il[t - 1] = ilo; il[t] = ihi;
        }
    }
}

// ---------------------------------------------------------------------------
// Phase 1: per-split distance scan + buffered exact top-16.
// Distance core uses sm_103a packed f32x2 ops: each half is an independent
// correctly-rounded fp32 op, so per-point bits match the XLA reference:
//   q2/o2: plain-rounded ((x*x + y*y) + z*z), no fma
//   cross: forward fma chain fma(z,oz, fma(y,oy, rn(x*ox)))
//   d2   : fmaf(-2, c, fadd(q2,o2))
// Tile stores point PAIRS: tileA = ((x0,x1),(y0,y1)), tileB = ((z0,z1),(o20,o21)).
// LDS.128 lands halves in aligned register pairs -> no pack MOVs in hot loop.
// 5 packed FP ops cover 2 points. Appends (lo half first, then hi) preserve
// ascending-index FIFO order; flushes batch insertion across lanes.
// ---------------------------------------------------------------------------
__global__ void __launch_bounds__(P1_THREADS, 7) knn_part_kernel(
    const float* __restrict__ orig, const float* __restrict__ query)
{
    __shared__ ulonglong2 tileA[TILE_PAIRS];       // 8 KB
    __shared__ ulonglong2 tileB[TILE_PAIRS];       // 8 KB
    __shared__ float  bufD[BUF][P1_THREADS];       // 7.5 KB
    __shared__ int    bufI[BUF][P1_THREADS];       // 7.5 KB

    const int b = blockIdx.y;
    const int s = blockIdx.z;
    const int tid = threadIdx.x;
    const int q = blockIdx.x * P1_THREADS + tid;
    const int mbase = s * SPLIT_M;

    const float* __restrict__ ox = orig + (size_t)b * 3 * M_;
    const float* __restrict__ oy = ox + M_;
    const float* __restrict__ oz = ox + 2 * M_;

    const float qx = query[(b * 3 + 0) * N_ + q];
    const float qy = query[(b * 3 + 1) * N_ + q];
    const float qz = query[(b * 3 + 2) * N_ + q];
    const float q2 = __fadd_rn(__fadd_rn(__fmul_rn(qx, qx), __fmul_rn(qy, qy)),
                               __fmul_rn(qz, qz));

    const ull qxx = pack2(qx, qx);
    const ull qyy = pack2(qy, qy);
    const ull qzz = pack2(qz, qz);
    const ull q22 = pack2(q2, q2);
    const ull neg2 = pack2(-2.0f, -2.0f);

    float dl[KNN_K];
    int   il[KNN_K];
    const float INF = __int_as_float(0x7f800000);
#pragma unroll
    for (int j = 0; j < KNN_K; ++j) { dl[j] = INF; il[j] = 0; }

    // running byte offset into bufD / bufI (row stride = P1_THREADS*4 bytes)
    char* const bD0 = (char*)&bufD[0][0] + tid * 4;
    char* const bI0 = (char*)&bufI[0][0] + tid * 4;
    int off = 0;
    const int offFlushLim = 3 * (P1_THREADS * 4);  // worst burst 3+8 = 11 <= 15

    for (int tb = 0; tb < SPLIT_M; tb += TILE1) {
        __syncthreads();
        for (int pp = tid; pp < TILE_PAIRS; pp += P1_THREADS) {
            int m = mbase + tb + 2 * pp;
            float x0 = ox[m], x1 = ox[m + 1];
            float y0 = oy[m], y1 = oy[m + 1];
            float z0 = oz[m], z1 = oz[m + 1];
            float o20 = __fadd_rn(__fadd_rn(__fmul_rn(x0, x0), __fmul_rn(y0, y0)),
                                  __fmul_rn(z0, z0));
            float o21 = __fadd_rn(__fadd_rn(__fmul_rn(x1, x1), __fmul_rn(y1, y1)),
                                  __fmul_rn(z1, z1));
            ulonglong2 A, Bv;
            A.x = pack2(x0, x1);
            A.y = pack2(y0, y1);
            Bv.x = pack2(z0, z1);
            Bv.y = pack2(o20, o21);
            tileA[pp] = A;
            tileB[pp] = Bv;
        }
        __syncthreads();

        for (int p0 = 0; p0 < TILE_PAIRS; p0 += 4) {
#pragma unroll
            for (int u = 0; u < 4; ++u) {
                ulonglong2 A = tileA[p0 + u];
                ulonglong2 Bv = tileB[p0 + u];
                // cross = fma(qz,z, fma(qy,y, rn(qx*x)))  per half
                ull cr = mul2(qxx, A.x);
                cr = fma2(qyy, A.y, cr);
                cr = fma2(qzz, Bv.x, cr);
                // d = fma(-2, cross, rn(q2 + o2))  per half
                ull ss = add2(q22, Bv.y);
                ull dd = fma2(neg2, cr, ss);
                float dlo, dhi;
                unpack2(dd, dlo, dhi);
                const int midx = mbase + tb + 2 * (p0 + u);
                if (dlo < dl[KNN_K - 1]) {
                    *(float*)(bD0 + off) = dlo;
                    *(int*)(bI0 + off) = midx;
                    off += P1_THREADS * 4;
                }
                if (dhi < dl[KNN_K - 1]) {
                    *(float*)(bD0 + off) = dhi;
                    *(int*)(bI0 + off) = midx + 1;
                    off += P1_THREADS * 4;
                }
            }
            if (__any_sync(FULLMASK, off > offFlushLim)) {
                const int c = off / (P1_THREADS * 4);
                for (int j = 0; j < c; ++j)
                    insert16(dl, il, bufD[j][tid], bufI[j][tid]);
                off = 0;
            }
        }
    }
    // tail flush
    {
        const int c = off / (P1_THREADS * 4);
        for (int j = 0; j < c; ++j)
            insert16(dl, il, bufD[j][tid], bufI[j][tid]);
    }

    const int gq = b * N_ + q;
#pragma unroll
    for (int j = 0; j < KNN_K; ++j) {
        g_cand_d[s][j][gq] = dl[j];
        g_cand_i[s][j][gq] = il[j];
    }
}

// ---------------------------------------------------------------------------
// Phase 2: stable 4-way merge of per-split sorted top-16 lists.
// Lexicographic (d, idx) == jax.lax.top_k tie-breaking (lowest index first).
// ---------------------------------------------------------------------------
__global__ void __launch_bounds__(128) knn_merge_kernel()
{
    const int q = blockIdx.x * 128 + threadIdx.x;   // global query id
    const float INF = __int_as_float(0x7f800000);

    float hd0 = g_cand_d[0][0][q], hd1 = g_cand_d[1][0][q];
    float hd2 = g_cand_d[2][0][q], hd3 = g_cand_d[3][0][q];
    int   hi0 = g_cand_i[0][0][q], hi1 = g_cand_i[1][0][q];
    int   hi2 = g_cand_i[2][0][q], hi3 = g_cand_i[3][0][q];
    int p0 = 0, p1 = 0, p2 = 0, p3 = 0;

    int* outp = g_knn_idx + (size_t)q * KNN_K;

#pragma unroll
    for (int step = 0; step < KNN_K; ++step) {
        bool a01 = (hd0 < hd1) || (hd0 == hd1 && hi0 < hi1);
        float dA = a01 ? hd0 : hd1;  int iA = a01 ? hi0 : hi1;
        bool a23 = (hd2 < hd3) || (hd2 == hd3 && hi2 < hi3);
        float dB = a23 ? hd2 : hd3;  int iB = a23 ? hi2 : hi3;
        bool aAB = (dA < dB) || (dA == dB && iA < iB);
        outp[step] = aAB ? iA : iB;
        if (aAB) {
            if (a01) {
                ++p0;
                if (p0 < KNN_K) { hd0 = g_cand_d[0][p0][q]; hi0 = g_cand_i[0][p0][q]; }
                else            { hd0 = INF; hi0 = 0x7fffffff; }
            } else {
                ++p1;
                if (p1 < KNN_K) { hd1 = g_cand_d[1][p1][q]; hi1 = g_cand_i[1][p1][q]; }
                else            { hd1 = INF; hi1 = 0x7fffffff; }
            }
        } else {
            if (a23) {
                ++p2;
                if (p2 < KNN_K) { hd2 = g_cand_d[2][p2][q]; hi2 = g_cand_i[2][p2][q]; }
                else            { hd2 = INF; hi2 = 0x7fffffff; }
            } else {
                ++p3;
                if (p3 < KNN_K) { hd3 = g_cand_d[3][p3][q]; hi3 = g_cand_i[3][p3][q]; }
                else            { hd3 = INF; hi3 = 0x7fffffff; }
            }
        }
    }
}

// ---------------------------------------------------------------------------
// Phase 3: fused MLP0 (3->64) + max-pool + MLP1 (64->64, k<4) + sigmoid gate
// + gather + weighted sum. Warp-per-query, BN folded. 8 warps/block.
// ---------------------------------------------------------------------------
__global__ void __launch_bounds__(S2_THREADS) fuse_kernel(
    const float* __restrict__ orig, const float* __restrict__ query,
    const float* __restrict__ local_feat,
    const float* __restrict__ w0, const float* __restrict__ b0,
    const float* __restrict__ g0, const float* __restrict__ be0,
    const float* __restrict__ m0, const float* __restrict__ v0,
    const float* __restrict__ w1, const float* __restrict__ b1,
    const float* __restrict__ g1, const float* __restrict__ be1,
    const float* __restrict__ m1, const float* __restrict__ v1,
    const float* __restrict__ w2, const float* __restrict__ b2,
    float* __restrict__ out)
{
    __shared__ float sW0[3][FEAT];
    __shared__ float sB0[FEAT];
    __shared__ float sW1[FEAT][FEAT + 1];   // +1 pad: conflict-free row reads
    __shared__ float sB1[FEAT];
    __shared__ float sW2[2 * FEAT];
    __shared__ float sS1[FEAT];
    __shared__ float sF0[S2_WARPS][FEAT][K4];  // [cp][k] -> float4 broadcast read

    const int tid = threadIdx.x;

    if (tid < FEAT) {
        float s0 = g0[tid] / sqrtf(v0[tid] + 1e-5f);
        sB0[tid] = (b0[tid] - m0[tid]) * s0 + be0[tid];
        sW0[0][tid] = w0[tid * 3 + 0] * s0;
        sW0[1][tid] = w0[tid * 3 + 1] * s0;
        sW0[2][tid] = w0[tid * 3 + 2] * s0;
        float s1 = g1[tid] / sqrtf(v1[tid] + 1e-5f);
        sS1[tid] = s1;
        sB1[tid] = (b1[tid] - m1[tid]) * s1 + be1[tid];
        sW2[tid] = w2[tid];
        sW2[tid + FEAT] = w2[tid + FEAT];
    }
    __syncthreads();
    for (int i = tid; i < FEAT * FEAT; i += S2_THREADS) {
        int ch = i >> 6;
        sW1[ch][i & 63] = w1[i] * sS1[ch];
    }
    __syncthreads();

    const int warp = tid >> 5;
    const int lane = tid & 31;
    const int qid = blockIdx.x * S2_WARPS + warp;
    const int b = qid >> 13;          // / N_
    const int n = qid & (N_ - 1);

    const int* kp = g_knn_idx + (size_t)qid * KNN_K;
    int kidx = (lane < KNN_K) ? kp[lane] : 0;

    const float qx = query[(b * 3 + 0) * N_ + n];
    const float qy = query[(b * 3 + 1) * N_ + n];
    const float qz = query[(b * 3 + 2) * N_ + n];

    float px = 0.f, py = 0.f, pz = 0.f;
    {
        const float* ob = orig + (size_t)b * 3 * M_;
        if (lane < KNN_K) {
            px = ob[kidx];
            py = ob[M_ + kidx];
            pz = ob[2 * M_ + kidx];
        }
    }

    const int c0 = lane, c1 = lane + 32;
    const float w0x0 = sW0[0][c0], w0y0 = sW0[1][c0], w0z0 = sW0[2][c0], bb00 = sB0[c0];
    const float w0x1 = sW0[0][c1], w0y1 = sW0[1][c1], w0z1 = sW0[2][c1], bb01 = sB0[c1];

    float fg0 = 0.f, fg1 = 0.f;   // relu >= 0 so 0 init == max

#pragma unroll
    for (int k = 0; k < KNN_K; ++k) {
        float rx = __shfl_sync(FULLMASK, px, k) - qx;
        float ry = __shfl_sync(FULLMASK, py, k) - qy;
        float rz = __shfl_sync(FULLMASK, pz, k) - qz;
        float a0 = fmaf(w0x0, rx, fmaf(w0y0, ry, fmaf(w0z0, rz, bb00)));
        float a1 = fmaf(w0x1, rx, fmaf(w0y1, ry, fmaf(w0z1, rz, bb01)));
        a0 = fmaxf(a0, 0.f);
        a1 = fmaxf(a1, 0.f);
        fg0 = fmaxf(fg0, a0);
        fg1 = fmaxf(fg1, a1);
        if (k < K4) {
            sF0[warp][c0][k] = a0;
            sF0[warp][c1][k] = a1;
        }
    }
    __syncwarp();

    const float bb10 = sB1[c0], bb11 = sB1[c1];
    float ra0 = bb10, ra1 = bb10, ra2 = bb10, ra3 = bb10;
    float rb0 = bb11, rb1 = bb11, rb2 = bb11, rb3 = bb11;
#pragma unroll
    for (int cp = 0; cp < FEAT; ++cp) {
        float wa = sW1[c0][cp];
        float wb = sW1[c1][cp];
        float4 f = *reinterpret_cast<const float4*>(&sF0[warp][cp][0]); // broadcast
        ra0 = fmaf(wa, f.x, ra0); ra1 = fmaf(wa, f.y, ra1);
        ra2 = fmaf(wa, f.z, ra2); ra3 = fmaf(wa, f.w, ra3);
        rb0 = fmaf(wb, f.x, rb0); rb1 = fmaf(wb, f.y, rb1);
        rb2 = fmaf(wb, f.z, rb2); rb3 = fmaf(wb, f.w, rb3);
    }
    float rf0[K4], rf1[K4];
    rf0[0] = fmaxf(ra0, 0.f); rf0[1] = fmaxf(ra1, 0.f);
    rf0[2] = fmaxf(ra2, 0.f); rf0[3] = fmaxf(ra3, 0.f);
    rf1[0] = fmaxf(rb0, 0.f); rf1[1] = fmaxf(rb1, 0.f);
    rf1[2] = fmaxf(rb2, 0.f); rf1[3] = fmaxf(rb3, 0.f);

    const float w2a = sW2[c0], w2b = sW2[c1];
    const float w2ga = sW2[FEAT + c0], w2gb = sW2[FEAT + c1];
    const float bias2 = b2[0];
    const float* lf = local_feat + (size_t)b * FEAT * M_;

    float o0 = 0.f, o1 = 0.f;
#pragma unroll
    for (int k = 0; k < K4; ++k) {
        float part = w2a * rf0[k] + w2b * rf1[k] + w2ga * fg0 + w2gb * fg1;
#pragma unroll
        for (int sdown = 16; sdown > 0; sdown >>= 1)
            part += __shfl_xor_sync(FULLMASK, part, sdown);
        float wk = 1.0f / (1.0f + expf(-(part + bias2)));
        int mk = __shfl_sync(FULLMASK, kidx, k);
        float pf0 = lf[(size_t)c0 * M_ + mk];
        float pf1 = lf[(size_t)c1 * M_ + mk];
        o0 += (1.0f - wk) * rf0[k] + wk * pf0;
        o1 += (1.0f - wk) * rf1[k] + wk * pf1;
    }

    out[((size_t)b * FEAT + c0) * N_ + n] = o0;
    out[((size_t)b * FEAT + c1) * N_ + n] = o1;
}

// ---------------------------------------------------------------------------
extern "C" void kernel_launch(void* const* d_in, const int* in_sizes, int n_in,
                              void* d_out, int out_size)
{
    (void)in_sizes; (void)n_in; (void)out_size;
    const float* orig  = (const float*)d_in[0];
    const float* query = (const float*)d_in[1];
    const float* lf    = (const float*)d_in[2];
    const float* w0 = (const float*)d_in[3];
    const float* b0 = (const float*)d_in[4];
    const float* g0 = (const float*)d_in[5];
    const float* be0 = (const float*)d_in[6];
    const float* m0 = (const float*)d_in[7];
    const float* v0 = (const float*)d_in[8];
    const float* w1 = (const float*)d_in[9];
    const float* b1 = (const float*)d_in[10];
    const float* g1 = (const float*)d_in[11];
    const float* be1 = (const float*)d_in[12];
    const float* m1 = (const float*)d_in[13];
    const float* v1 = (const float*)d_in[14];
    const float* w2 = (const float*)d_in[15];
    const float* b2 = (const float*)d_in[16];
    float* out = (float*)d_out;

    dim3 g1d(N_ / P1_THREADS, B_, S_);
    knn_part_kernel<<<g1d, P1_THREADS>>>(orig, query);

    knn_merge_kernel<<<(B_ * N_) / 128, 128>>>();

    fuse_kernel<<<(B_ * N_) / S2_WARPS, S2_THREADS>>>(
        orig, query, lf,
        w0, b0, g0, be0, m0, v0,
        w1, b1, g1, be1, m1, v1,
        w2, b2, out);
}